// round 12
// baseline (speedup 1.0000x reference)
#include <cuda_runtime.h>
#include <cstdint>

// out[b, j] = relu( sum_d x[b,d] * (gamma*W3[j,d] + W4[j,d]) )
// softmax over size-1 axis == 1 -> attention collapses; W1/W2 dead; reshapes are
// flat-order-preserving so res == x @ W3^T exactly.
//
// R5 lesson: LDS broadcast is charged per LANE-BYTE (~4.6 wf per LDS.128), and the
// smem pipeline's barriers left a 12.5-warp/SM kernel latency-bound at 2.3x its
// floors. Global-load coalescer DOES merge same-address lanes -> broadcast LDG.128
// costs ~1-2 wf. So: drop smem + barriers entirely, read x via __ldg (L1-resident,
// 2.5KB/tile), keep weights in registers, row-pair-local accumulators for ILP.

#define B_ROWS    262144
#define DICTD     20
#define JCOLS     200
#define RPT       8                       // rows per thread (per tile)
#define CPT       4                       // cols per thread
#define TILE_ROWS 32
#define NGROUPS   (TILE_ROWS / RPT)       // 4 row-groups
#define NQUADS    (JCOLS / CPT)           // 50 col-quads
#define NTHREADS  (NGROUPS * NQUADS)      // 200
#define NTILES    (B_ROWS / TILE_ROWS)    // 8192
#define NBLOCKS   296                     // 2 resident per SM

typedef unsigned long long ull;

__device__ __forceinline__ ull pack2(float lo, float hi) {
    ull r;
    asm("mov.b64 %0, {%1, %2};" : "=l"(r) : "f"(lo), "f"(hi));
    return r;
}
// Packed dual fp32 FMA (sm_100+); 2 MACs/inst, rt_SMSP=2 (2x scalar FFMA throughput).
__device__ __forceinline__ ull fma2(ull a, ull b, ull c) {
    ull d;
    asm("fma.rn.f32x2 %0, %1, %2, %3;" : "=l"(d) : "l"(a), "l"(b), "l"(c));
    return d;
}
__device__ __forceinline__ void prefetch_l2(const void* p) {
    asm volatile("prefetch.global.L2 [%0];" :: "l"(p));
}

__global__ void __launch_bounds__(NTHREADS, 2)
fused_relu_gemm_kernel(const float* __restrict__ x,
                       const float* __restrict__ W3,
                       const float* __restrict__ W4,
                       const float* __restrict__ gamma,
                       float* __restrict__ out)
{
    const int tid = threadIdx.x;
    const int g   = tid / NQUADS;          // 0..3  row-group (8 rows)
    const int q   = tid % NQUADS;          // 0..49 col-quad
    const int j0  = q * CPT;

    // ---- one-time: effective weights for 4 owned columns as f32x2 pairs ----
    const float gm = __ldg(gamma);
    ull w0[DICTD], w1[DICTD];              // (j0,j0+1) and (j0+2,j0+3)
#pragma unroll
    for (int d = 0; d < DICTD; d++) {
        float a = fmaf(gm, __ldg(&W3[(j0 + 0) * DICTD + d]), __ldg(&W4[(j0 + 0) * DICTD + d]));
        float b = fmaf(gm, __ldg(&W3[(j0 + 1) * DICTD + d]), __ldg(&W4[(j0 + 1) * DICTD + d]));
        float c = fmaf(gm, __ldg(&W3[(j0 + 2) * DICTD + d]), __ldg(&W4[(j0 + 2) * DICTD + d]));
        float e = fmaf(gm, __ldg(&W3[(j0 + 3) * DICTD + d]), __ldg(&W4[(j0 + 3) * DICTD + d]));
        w0[d] = pack2(a, b);
        w1[d] = pack2(c, e);
    }

    for (int tile = blockIdx.x; tile < NTILES; tile += NBLOCKS) {
        const int   rowbase = tile * TILE_ROWS + g * RPT;
        const float* xrow   = x + rowbase * DICTD;      // 8 rows x 20 floats, 16B-aligned

        // hide next tile's DRAM latency (8 rows = 640B spans <= 6 lines; 3 probes)
        const int nt = tile + NBLOCKS;
        if (nt < NTILES) {
            const float* nx = x + (nt * TILE_ROWS + g * RPT) * DICTD;
            prefetch_l2(nx);
            prefetch_l2(nx + 3 * DICTD);
            prefetch_l2(nx + 6 * DICTD);
        }

#pragma unroll
        for (int rp = 0; rp < RPT / 2; rp++) {          // row pairs: 4 fma chains
            const float4* ra = reinterpret_cast<const float4*>(xrow + (2 * rp + 0) * DICTD);
            const float4* rb = reinterpret_cast<const float4*>(xrow + (2 * rp + 1) * DICTD);
            ull aA0 = 0, aA1 = 0, aB0 = 0, aB1 = 0;
#pragma unroll
            for (int db = 0; db < DICTD / 4; db++) {    // 5 blocks of 4 d's
                // broadcast LDG.128: all lanes of a g-cohort hit the same sector
                const float4 va = __ldg(&ra[db]);
                const float4 vb = __ldg(&rb[db]);
                const int d = db * 4;
                ull t;
                t = pack2(va.x, va.x); aA0 = fma2(t, w0[d + 0], aA0); aA1 = fma2(t, w1[d + 0], aA1);
                t = pack2(va.y, va.y); aA0 = fma2(t, w0[d + 1], aA0); aA1 = fma2(t, w1[d + 1], aA1);
                t = pack2(va.z, va.z); aA0 = fma2(t, w0[d + 2], aA0); aA1 = fma2(t, w1[d + 2], aA1);
                t = pack2(va.w, va.w); aA0 = fma2(t, w0[d + 3], aA0); aA1 = fma2(t, w1[d + 3], aA1);
                t = pack2(vb.x, vb.x); aB0 = fma2(t, w0[d + 0], aB0); aB1 = fma2(t, w1[d + 0], aB1);
                t = pack2(vb.y, vb.y); aB0 = fma2(t, w0[d + 1], aB0); aB1 = fma2(t, w1[d + 1], aB1);
                t = pack2(vb.z, vb.z); aB0 = fma2(t, w0[d + 2], aB0); aB1 = fma2(t, w1[d + 2], aB1);
                t = pack2(vb.w, vb.w); aB0 = fma2(t, w0[d + 3], aB0); aB1 = fma2(t, w1[d + 3], aB1);
            }
            // relu + coalesced STG.128 (lanes = consecutive quads), spread through loop
            {
                float2 f0 = *reinterpret_cast<float2*>(&aA0);
                float2 f1 = *reinterpret_cast<float2*>(&aA1);
                *reinterpret_cast<float4*>(&out[(rowbase + 2 * rp + 0) * JCOLS + j0]) =
                    make_float4(fmaxf(f0.x, 0.f), fmaxf(f0.y, 0.f),
                                fmaxf(f1.x, 0.f), fmaxf(f1.y, 0.f));
            }
            {
                float2 f0 = *reinterpret_cast<float2*>(&aB0);
                float2 f1 = *reinterpret_cast<float2*>(&aB1);
                *reinterpret_cast<float4*>(&out[(rowbase + 2 * rp + 1) * JCOLS + j0]) =
                    make_float4(fmaxf(f0.x, 0.f), fmaxf(f0.y, 0.f),
                                fmaxf(f1.x, 0.f), fmaxf(f1.y, 0.f));
            }
        }
    }
}

extern "C" void kernel_launch(void* const* d_in, const int* in_sizes, int n_in,
                              void* d_out, int out_size)
{
    // metadata order: x, W1, W2, W3, W4, gamma  (W1/W2 mathematically dead)
    const float* x     = (const float*)d_in[0];
    const float* W3    = (const float*)d_in[3];
    const float* W4    = (const float*)d_in[4];
    const float* gamma = (const float*)d_in[5];
    float*       out   = (float*)d_out;

    fused_relu_gemm_kernel<<<NBLOCKS, NTHREADS>>>(x, W3, W4, gamma, out);
}